// round 1
// baseline (speedup 1.0000x reference)
#include <cuda_runtime.h>
#include <cuda_bf16.h>

#define NNODES 50000
#define NEDGES 800000
#define ETOT   (NNODES + NEDGES)
#define HEADS  4
#define HID    64
#define HH     256   // HEADS*HID
#define INC    128
#define OUTC   128

// ---------------- scratch (device globals; no allocation) ----------------
__device__ float g_H  [NNODES * HH];   // transformed features [N,4,64]
__device__ float g_ACC[NNODES * HH];   // segment-sum accumulator
__device__ float g_ES [NNODES * HEADS];
__device__ float g_ED [NNODES * HEADS];
__device__ float g_DEN[NNODES * HEADS];
__device__ float g_W  [ETOT * HEADS];  // per-edge exp weights
__device__ float g_F1 [NNODES * HID];
__device__ float g_F2 [NNODES * HID];

// ---------------- tiled SIMT fp32 GEMM: C[M,Nn] = A[M,K] @ B[K,Nn] (+bias) ----
// BM=BN=64, BK=16, 256 threads, 4x4 per thread. K % 16 == 0, Nn % 64 == 0.
__global__ void sgemm64(const float* __restrict__ A, const float* __restrict__ B,
                        float* __restrict__ C, int M, int Nn, int K,
                        const float* __restrict__ bias) {
    const int BM = 64, BN = 64, BK = 16, TM = 4, TN = 4;
    __shared__ float As[BK][BM];
    __shared__ float Bs[BK][BN];
    int tid  = threadIdx.x;                  // 0..255
    int brow = blockIdx.y * BM;
    int bcol = blockIdx.x * BN;
    int tr = (tid / (BN / TN)) * TM;         // 0..60 step 4
    int tc = (tid % (BN / TN)) * TN;
    float acc[TM][TN] = {};

    for (int k0 = 0; k0 < K; k0 += BK) {
        #pragma unroll
        for (int i = tid; i < BM * BK; i += 256) {
            int r = i / BK, c = i % BK;
            int gr = brow + r;
            As[c][r] = (gr < M) ? A[(long)gr * K + k0 + c] : 0.f;
        }
        #pragma unroll
        for (int i = tid; i < BK * BN; i += 256) {
            int r = i / BN, c = i % BN;
            Bs[r][c] = B[(long)(k0 + r) * Nn + bcol + c];
        }
        __syncthreads();
        #pragma unroll
        for (int k = 0; k < BK; k++) {
            float a[TM], b[TN];
            #pragma unroll
            for (int i = 0; i < TM; i++) a[i] = As[k][tr + i];
            #pragma unroll
            for (int j = 0; j < TN; j++) b[j] = Bs[k][tc + j];
            #pragma unroll
            for (int i = 0; i < TM; i++)
                #pragma unroll
                for (int j = 0; j < TN; j++) acc[i][j] += a[i] * b[j];
        }
        __syncthreads();
    }
    #pragma unroll
    for (int i = 0; i < TM; i++) {
        int gr = brow + tr + i;
        if (gr < M) {
            #pragma unroll
            for (int j = 0; j < TN; j++) {
                float v = acc[i][j];
                if (bias) v += bias[bcol + tc + j];
                C[(long)gr * Nn + bcol + tc + j] = v;
            }
        }
    }
}

// ---------------- per-(node,head) attention logit dots ----------------
__global__ void scores_k(const float* __restrict__ H, const float* __restrict__ asrc,
                         const float* __restrict__ adst, float* __restrict__ es,
                         float* __restrict__ ed, int NH) {
    int gw   = (blockIdx.x * blockDim.x + threadIdx.x) >> 5;
    int lane = threadIdx.x & 31;
    if (gw >= NH) return;
    int node = gw >> 2, head = gw & 3;
    const float* hp = H + (long)node * HH + head * HID;
    const float* as = asrc + head * HID;
    const float* ad = adst + head * HID;
    float h0 = hp[lane], h1 = hp[lane + 32];
    float s1 = h0 * as[lane] + h1 * as[lane + 32];
    float s2 = h0 * ad[lane] + h1 * ad[lane + 32];
    #pragma unroll
    for (int o = 16; o > 0; o >>= 1) {
        s1 += __shfl_xor_sync(0xffffffffu, s1, o);
        s2 += __shfl_xor_sync(0xffffffffu, s2, o);
    }
    if (lane == 0) { es[gw] = s1; ed[gw] = s2; }
}

// ---------------- edge pass 1: w = exp(leakyrelu(es[s]+ed[d])); den[d] += w ----
__global__ void edge_w_k(const int* __restrict__ ei, const float* __restrict__ es,
                         const float* __restrict__ ed, float* __restrict__ w,
                         float* __restrict__ den, int Ein, int Etot) {
    int e = blockIdx.x * blockDim.x + threadIdx.x;
    if (e >= Etot) return;
    int s, d;
    if (e < Ein) { s = ei[e]; d = ei[Ein + e]; }
    else         { s = d = e - Ein; }
    #pragma unroll
    for (int h = 0; h < HEADS; h++) {
        float v = es[s * HEADS + h] + ed[d * HEADS + h];
        v = (v > 0.f) ? v : 0.2f * v;
        float ew = expf(v);                 // no max-subtraction needed: |v| is O(1..10)
        w[(long)e * HEADS + h] = ew;
        atomicAdd(&den[d * HEADS + h], ew);
    }
}

// ---------------- edge pass 2: acc[d] += h[s] * alpha  (float4 RED atomics) ----
// 64 threads per edge; each thread handles one float4 (4 channels).
__global__ void scatter_k(const int* __restrict__ ei, const float* __restrict__ H,
                          const float* __restrict__ w, const float* __restrict__ den,
                          float* __restrict__ acc, int Ein, int Etot) {
    int t = blockIdx.x * blockDim.x + threadIdx.x;
    int e = t >> 6;
    if (e >= Etot) return;
    int q = t & 63;                 // float4 slot 0..63 across 256 channels
    int s, d;
    if (e < Ein) { s = ei[e]; d = ei[Ein + e]; }
    else         { s = d = e - Ein; }
    int head = q >> 4;              // 16 float4s per head
    float alpha = w[(long)e * HEADS + head] / den[d * HEADS + head];
    float4 hv = reinterpret_cast<const float4*>(H + (long)s * HH)[q];
    float4 m  = make_float4(hv.x * alpha, hv.y * alpha, hv.z * alpha, hv.w * alpha);
    atomicAdd(reinterpret_cast<float4*>(acc + (long)d * HH) + q, m);
}

// ---------------- head-mean + bias + LayerNorm + ReLU (warp per node) --------
__global__ void finalize_k(const float* __restrict__ acc, const float* __restrict__ b,
                           const float* __restrict__ g, const float* __restrict__ be,
                           float* __restrict__ out, int Nn) {
    int warp = (blockIdx.x * blockDim.x + threadIdx.x) >> 5;
    int lane = threadIdx.x & 31;
    if (warp >= Nn) return;
    const float* a = acc + (long)warp * HH;
    float v[2];
    #pragma unroll
    for (int i = 0; i < 2; i++) {
        int c = lane + i * 32;
        v[i] = (a[c] + a[64 + c] + a[128 + c] + a[192 + c]) * 0.25f + b[c];
    }
    float s = v[0] + v[1], ss = v[0] * v[0] + v[1] * v[1];
    #pragma unroll
    for (int o = 16; o > 0; o >>= 1) {
        s  += __shfl_xor_sync(0xffffffffu, s, o);
        ss += __shfl_xor_sync(0xffffffffu, ss, o);
    }
    float mean = s * (1.f / 64.f);
    float var  = ss * (1.f / 64.f) - mean * mean;
    float inv  = rsqrtf(var + 1e-5f);
    #pragma unroll
    for (int i = 0; i < 2; i++) {
        int c = lane + i * 32;
        float o2 = (v[i] - mean) * inv * g[c] + be[c];
        out[(long)warp * HID + c] = fmaxf(o2, 0.f);
    }
}

// ---------------------------------------------------------------------------
extern "C" void kernel_launch(void* const* d_in, const int* in_sizes, int n_in,
                              void* d_out, int out_size) {
    const float* x     = (const float*)d_in[0];
    const int*   ei    = (const int*)  d_in[1];
    const float* W1    = (const float*)d_in[2];
    const float* asrc1 = (const float*)d_in[3];
    const float* adst1 = (const float*)d_in[4];
    const float* b1    = (const float*)d_in[5];
    const float* g1    = (const float*)d_in[6];
    const float* be1   = (const float*)d_in[7];
    const float* W2    = (const float*)d_in[8];
    const float* asrc2 = (const float*)d_in[9];
    const float* adst2 = (const float*)d_in[10];
    const float* b2    = (const float*)d_in[11];
    const float* g2    = (const float*)d_in[12];
    const float* be2   = (const float*)d_in[13];
    const float* Wo    = (const float*)d_in[14];
    const float* bo    = (const float*)d_in[15];
    float* out = (float*)d_out;

    const int Nn   = in_sizes[0] / INC;      // 50000
    const int Ein  = in_sizes[1] / 2;        // 800000
    const int Etot = Ein + Nn;               // 850000
    const int NH   = Nn * HEADS;

    float *H, *ACC, *ES, *ED, *DEN, *W, *F1, *F2;
    cudaGetSymbolAddress((void**)&H,   g_H);
    cudaGetSymbolAddress((void**)&ACC, g_ACC);
    cudaGetSymbolAddress((void**)&ES,  g_ES);
    cudaGetSymbolAddress((void**)&ED,  g_ED);
    cudaGetSymbolAddress((void**)&DEN, g_DEN);
    cudaGetSymbolAddress((void**)&W,   g_W);
    cudaGetSymbolAddress((void**)&F1,  g_F1);
    cudaGetSymbolAddress((void**)&F2,  g_F2);

    dim3 gemm1_grid(HH / 64, (Nn + 63) / 64);      // x@W1  -> H
    dim3 gemm2_grid(HH / 64, (Nn + 63) / 64);      // F1@W2 -> H
    dim3 gemmo_grid(OUTC / 64, (Nn + 63) / 64);    // F2@Wo -> out

    int score_blocks = (NH * 32 + 255) / 256;
    int ew_blocks    = (Etot + 255) / 256;
    int sc_blocks    = (Etot * 64 + 255) / 256;
    int fin_blocks   = (Nn * 32 + 255) / 256;

    // ---------------- layer 1 ----------------
    sgemm64<<<gemm1_grid, 256>>>(x, W1, H, Nn, HH, INC, nullptr);
    scores_k<<<score_blocks, 256>>>(H, asrc1, adst1, ES, ED, NH);
    cudaMemsetAsync(DEN, 0, (size_t)NH * sizeof(float), 0);
    cudaMemsetAsync(ACC, 0, (size_t)Nn * HH * sizeof(float), 0);
    edge_w_k<<<ew_blocks, 256>>>(ei, ES, ED, W, DEN, Ein, Etot);
    scatter_k<<<sc_blocks, 256>>>(ei, H, W, DEN, ACC, Ein, Etot);
    finalize_k<<<fin_blocks, 256>>>(ACC, b1, g1, be1, F1, Nn);

    // ---------------- layer 2 ----------------
    sgemm64<<<gemm2_grid, 256>>>(F1, W2, H, Nn, HH, HID, nullptr);
    scores_k<<<score_blocks, 256>>>(H, asrc2, adst2, ES, ED, NH);
    cudaMemsetAsync(DEN, 0, (size_t)NH * sizeof(float), 0);
    cudaMemsetAsync(ACC, 0, (size_t)Nn * HH * sizeof(float), 0);
    edge_w_k<<<ew_blocks, 256>>>(ei, ES, ED, W, DEN, Ein, Etot);
    scatter_k<<<sc_blocks, 256>>>(ei, H, W, DEN, ACC, Ein, Etot);
    finalize_k<<<fin_blocks, 256>>>(ACC, b2, g2, be2, F2, Nn);

    // ---------------- output projection ----------------
    sgemm64<<<gemmo_grid, 256>>>(F2, Wo, out, Nn, OUTC, HID, bo);
}

// round 2
// speedup vs baseline: 1.8603x; 1.8603x over previous
#include <cuda_runtime.h>
#include <cuda_bf16.h>

#define NNODES 50000
#define NEDGES 800000
#define ETOT   (NNODES + NEDGES)
#define HEADS  4
#define HID    64
#define HH     256   // HEADS*HID
#define INC    128
#define OUTC   128

// ---------------- scratch (device globals; no allocation) ----------------
__device__ float g_H  [NNODES * HH];      // transformed features [N,4,64]
__device__ float g_ES [NNODES * HEADS];
__device__ float g_ED [NNODES * HEADS];
__device__ float g_F1 [NNODES * HID];
__device__ float g_F2 [NNODES * HID];
__device__ int   g_DEG[NNODES];
__device__ int   g_CUR[NNODES];
__device__ int   g_ROW[NNODES + 1];
__device__ int   g_COL[ETOT];             // src node id per CSR-sorted edge

// ---------------- tiled SIMT fp32 GEMM: C[M,Nn] = A[M,K] @ B[K,Nn] (+bias) ----
__global__ void sgemm64(const float* __restrict__ A, const float* __restrict__ B,
                        float* __restrict__ C, int M, int Nn, int K,
                        const float* __restrict__ bias) {
    const int BM = 64, BN = 64, BK = 16, TM = 4, TN = 4;
    __shared__ float As[BK][BM];
    __shared__ float Bs[BK][BN];
    int tid  = threadIdx.x;
    int brow = blockIdx.y * BM;
    int bcol = blockIdx.x * BN;
    int tr = (tid / (BN / TN)) * TM;
    int tc = (tid % (BN / TN)) * TN;
    float acc[TM][TN] = {};

    for (int k0 = 0; k0 < K; k0 += BK) {
        #pragma unroll
        for (int i = tid; i < BM * BK; i += 256) {
            int r = i / BK, c = i % BK;
            int gr = brow + r;
            As[c][r] = (gr < M) ? A[(long)gr * K + k0 + c] : 0.f;
        }
        #pragma unroll
        for (int i = tid; i < BK * BN; i += 256) {
            int r = i / BN, c = i % BN;
            Bs[r][c] = B[(long)(k0 + r) * Nn + bcol + c];
        }
        __syncthreads();
        #pragma unroll
        for (int k = 0; k < BK; k++) {
            float a[TM], b[TN];
            #pragma unroll
            for (int i = 0; i < TM; i++) a[i] = As[k][tr + i];
            #pragma unroll
            for (int j = 0; j < TN; j++) b[j] = Bs[k][tc + j];
            #pragma unroll
            for (int i = 0; i < TM; i++)
                #pragma unroll
                for (int j = 0; j < TN; j++) acc[i][j] += a[i] * b[j];
        }
        __syncthreads();
    }
    #pragma unroll
    for (int i = 0; i < TM; i++) {
        int gr = brow + tr + i;
        if (gr < M) {
            #pragma unroll
            for (int j = 0; j < TN; j++) {
                float v = acc[i][j];
                if (bias) v += bias[bcol + tc + j];
                C[(long)gr * Nn + bcol + tc + j] = v;
            }
        }
    }
}

// ---------------- per-(node,head) attention logit dots ----------------
__global__ void scores_k(const float* __restrict__ H, const float* __restrict__ asrc,
                         const float* __restrict__ adst, float* __restrict__ es,
                         float* __restrict__ ed, int NH) {
    int gw   = (blockIdx.x * blockDim.x + threadIdx.x) >> 5;
    int lane = threadIdx.x & 31;
    if (gw >= NH) return;
    int node = gw >> 2, head = gw & 3;
    const float* hp = H + (long)node * HH + head * HID;
    const float* as = asrc + head * HID;
    const float* ad = adst + head * HID;
    float h0 = hp[lane], h1 = hp[lane + 32];
    float s1 = h0 * as[lane] + h1 * as[lane + 32];
    float s2 = h0 * ad[lane] + h1 * ad[lane + 32];
    #pragma unroll
    for (int o = 16; o > 0; o >>= 1) {
        s1 += __shfl_xor_sync(0xffffffffu, s1, o);
        s2 += __shfl_xor_sync(0xffffffffu, s2, o);
    }
    if (lane == 0) { es[gw] = s1; ed[gw] = s2; }
}

// ---------------- CSR build: degree histogram ----------------
__global__ void deg_k(const int* __restrict__ ei, int* __restrict__ deg,
                      int Ein, int Etot) {
    int e = blockIdx.x * blockDim.x + threadIdx.x;
    if (e >= Etot) return;
    int d = (e < Ein) ? ei[Ein + e] : e - Ein;
    atomicAdd(&deg[d], 1);
}

// ---------------- CSR build: single-block exclusive scan ----------------
__global__ void scan_k(const int* __restrict__ deg, int* __restrict__ rowptr, int Nn) {
    __shared__ int wsum[32];
    __shared__ int carry;
    int t = threadIdx.x, lane = t & 31, wid = t >> 5;
    if (t == 0) carry = 0;
    __syncthreads();
    for (int base = 0; base < Nn; base += 1024) {
        int i = base + t;
        int v = (i < Nn) ? deg[i] : 0;
        int x = v;
        #pragma unroll
        for (int o = 1; o < 32; o <<= 1) {
            int y = __shfl_up_sync(0xffffffffu, x, o);
            if (lane >= o) x += y;
        }
        if (lane == 31) wsum[wid] = x;
        __syncthreads();
        if (wid == 0) {
            int s = wsum[lane];
            #pragma unroll
            for (int o = 1; o < 32; o <<= 1) {
                int y = __shfl_up_sync(0xffffffffu, s, o);
                if (lane >= o) s += y;
            }
            wsum[lane] = s;
        }
        __syncthreads();
        int off = carry + (wid > 0 ? wsum[wid - 1] : 0);
        if (i < Nn) rowptr[i] = off + x - v;
        int tot = wsum[31];
        __syncthreads();
        if (t == 0) carry += tot;
        __syncthreads();
    }
    if (t == 0) rowptr[Nn] = carry;
}

// ---------------- CSR build: fill column (src) lists ----------------
__global__ void fill_k(const int* __restrict__ ei, int* __restrict__ cursor,
                       const int* __restrict__ rowptr, int* __restrict__ colsrc,
                       int Ein, int Etot) {
    int e = blockIdx.x * blockDim.x + threadIdx.x;
    if (e >= Etot) return;
    int s, d;
    if (e < Ein) { s = ei[e]; d = ei[Ein + e]; }
    else         { s = d = e - Ein; }
    int p = atomicAdd(&cursor[d], 1);
    colsrc[rowptr[d] + p] = s;
}

// ---------------- fused gather: softmax-weighted aggregate + head-mean
// + bias + LayerNorm + ReLU.  One warp per destination node. ----------------
__global__ void gather_k(const float* __restrict__ H, const int* __restrict__ rowptr,
                         const int* __restrict__ colsrc, const float* __restrict__ es,
                         const float* __restrict__ ed, const float* __restrict__ b,
                         const float* __restrict__ g, const float* __restrict__ be,
                         float* __restrict__ out, int Nn) {
    int warp = (blockIdx.x * blockDim.x + threadIdx.x) >> 5;
    int lane = threadIdx.x & 31;
    if (warp >= Nn) return;
    const int d  = warp;
    const int hA = lane >> 4;      // head for float4 slot `lane`   (0 or 1)
    const int hB = hA + 2;         // head for float4 slot `lane+32` (2 or 3)

    float edv = (lane < 4) ? ed[d * 4 + lane] : 0.f;

    float4 acc1 = make_float4(0.f, 0.f, 0.f, 0.f);
    float4 acc2 = make_float4(0.f, 0.f, 0.f, 0.f);
    float denA = 0.f, denB = 0.f;

    int beg = rowptr[d], end = rowptr[d + 1];
    const float4* __restrict__ H4 = reinterpret_cast<const float4*>(H);

    int s = colsrc[beg];
    for (int e = beg; e < end; e++) {
        int s_next = (e + 1 < end) ? colsrc[e + 1] : 0;
        float w = 0.f;
        if (lane < 4) {
            float v = es[s * 4 + lane] + edv;
            v = (v > 0.f) ? v : 0.2f * v;
            w = __expf(v);
        }
        float wA = __shfl_sync(0xffffffffu, w, hA);
        float wB = __shfl_sync(0xffffffffu, w, hB);
        denA += wA; denB += wB;
        float4 h1 = H4[(long)s * 64 + lane];
        float4 h2 = H4[(long)s * 64 + lane + 32];
        acc1.x += wA * h1.x; acc1.y += wA * h1.y;
        acc1.z += wA * h1.z; acc1.w += wA * h1.w;
        acc2.x += wB * h2.x; acc2.y += wB * h2.y;
        acc2.z += wB * h2.z; acc2.w += wB * h2.w;
        s = s_next;
    }

    // normalize per head and combine this lane's two heads
    float rA = 1.f / denA, rB = 1.f / denB;
    float4 s4;
    s4.x = acc1.x * rA + acc2.x * rB;
    s4.y = acc1.y * rA + acc2.y * rB;
    s4.z = acc1.z * rA + acc2.z * rB;
    s4.w = acc1.w * rA + acc2.w * rB;
    // add partner lane (same channels, other head pair)
    s4.x += __shfl_xor_sync(0xffffffffu, s4.x, 16);
    s4.y += __shfl_xor_sync(0xffffffffu, s4.y, 16);
    s4.z += __shfl_xor_sync(0xffffffffu, s4.z, 16);
    s4.w += __shfl_xor_sync(0xffffffffu, s4.w, 16);

    int ch = (lane & 15) * 4;
    s4.x = s4.x * 0.25f + b[ch + 0];
    s4.y = s4.y * 0.25f + b[ch + 1];
    s4.z = s4.z * 0.25f + b[ch + 2];
    s4.w = s4.w * 0.25f + b[ch + 3];

    // LayerNorm over 64 channels (each channel duplicated on lanes L and L^16)
    float sum = s4.x + s4.y + s4.z + s4.w;
    float ssq = s4.x * s4.x + s4.y * s4.y + s4.z * s4.z + s4.w * s4.w;
    #pragma unroll
    for (int o = 16; o > 0; o >>= 1) {
        sum += __shfl_xor_sync(0xffffffffu, sum, o);
        ssq += __shfl_xor_sync(0xffffffffu, ssq, o);
    }
    float mean = sum * (1.f / 128.f);             // /2 for duplication, /64 channels
    float var  = ssq * (1.f / 128.f) - mean * mean;
    float inv  = rsqrtf(var + 1e-5f);

    s4.x = fmaxf((s4.x - mean) * inv * g[ch + 0] + be[ch + 0], 0.f);
    s4.y = fmaxf((s4.y - mean) * inv * g[ch + 1] + be[ch + 1], 0.f);
    s4.z = fmaxf((s4.z - mean) * inv * g[ch + 2] + be[ch + 2], 0.f);
    s4.w = fmaxf((s4.w - mean) * inv * g[ch + 3] + be[ch + 3], 0.f);

    if (lane < 16)
        reinterpret_cast<float4*>(out + (long)d * HID)[lane] = s4;
}

// ---------------------------------------------------------------------------
extern "C" void kernel_launch(void* const* d_in, const int* in_sizes, int n_in,
                              void* d_out, int out_size) {
    const float* x     = (const float*)d_in[0];
    const int*   ei    = (const int*)  d_in[1];
    const float* W1    = (const float*)d_in[2];
    const float* asrc1 = (const float*)d_in[3];
    const float* adst1 = (const float*)d_in[4];
    const float* b1    = (const float*)d_in[5];
    const float* g1    = (const float*)d_in[6];
    const float* be1   = (const float*)d_in[7];
    const float* W2    = (const float*)d_in[8];
    const float* asrc2 = (const float*)d_in[9];
    const float* adst2 = (const float*)d_in[10];
    const float* b2    = (const float*)d_in[11];
    const float* g2    = (const float*)d_in[12];
    const float* be2   = (const float*)d_in[13];
    const float* Wo    = (const float*)d_in[14];
    const float* bo    = (const float*)d_in[15];
    float* out = (float*)d_out;

    const int Nn   = in_sizes[0] / INC;      // 50000
    const int Ein  = in_sizes[1] / 2;        // 800000
    const int Etot = Ein + Nn;               // 850000
    const int NH   = Nn * HEADS;

    float *H, *ES, *ED, *F1, *F2;
    int *DEG, *CUR, *ROW, *COL;
    cudaGetSymbolAddress((void**)&H,   g_H);
    cudaGetSymbolAddress((void**)&ES,  g_ES);
    cudaGetSymbolAddress((void**)&ED,  g_ED);
    cudaGetSymbolAddress((void**)&F1,  g_F1);
    cudaGetSymbolAddress((void**)&F2,  g_F2);
    cudaGetSymbolAddress((void**)&DEG, g_DEG);
    cudaGetSymbolAddress((void**)&CUR, g_CUR);
    cudaGetSymbolAddress((void**)&ROW, g_ROW);
    cudaGetSymbolAddress((void**)&COL, g_COL);

    dim3 gemm1_grid(HH / 64, (Nn + 63) / 64);
    dim3 gemm2_grid(HH / 64, (Nn + 63) / 64);
    dim3 gemmo_grid(OUTC / 64, (Nn + 63) / 64);

    int score_blocks = (NH * 32 + 255) / 256;
    int edge_blocks  = (Etot + 255) / 256;
    int node_warpblk = (Nn * 32 + 255) / 256;

    // ---------------- CSR build (shared by both layers) ----------------
    cudaMemsetAsync(DEG, 0, (size_t)Nn * sizeof(int), 0);
    cudaMemsetAsync(CUR, 0, (size_t)Nn * sizeof(int), 0);
    deg_k<<<edge_blocks, 256>>>(ei, DEG, Ein, Etot);
    scan_k<<<1, 1024>>>(DEG, ROW, Nn);
    fill_k<<<edge_blocks, 256>>>(ei, CUR, ROW, COL, Ein, Etot);

    // ---------------- layer 1 ----------------
    sgemm64<<<gemm1_grid, 256>>>(x, W1, H, Nn, HH, INC, nullptr);
    scores_k<<<score_blocks, 256>>>(H, asrc1, adst1, ES, ED, NH);
    gather_k<<<node_warpblk, 256>>>(H, ROW, COL, ES, ED, b1, g1, be1, F1, Nn);

    // ---------------- layer 2 ----------------
    sgemm64<<<gemm2_grid, 256>>>(F1, W2, H, Nn, HH, HID, nullptr);
    scores_k<<<score_blocks, 256>>>(H, asrc2, adst2, ES, ED, NH);
    gather_k<<<node_warpblk, 256>>>(H, ROW, COL, ES, ED, b2, g2, be2, F2, Nn);

    // ---------------- output projection ----------------
    sgemm64<<<gemmo_grid, 256>>>(F2, Wo, out, Nn, OUTC, HID, bo);
}

// round 3
// speedup vs baseline: 2.2442x; 1.2064x over previous
#include <cuda_runtime.h>
#include <cuda_bf16.h>

#define NNODES 50000
#define NEDGES 800000
#define ETOT   (NNODES + NEDGES)
#define HEADS  4
#define HID    64
#define HH     256   // HEADS*HID
#define INC    128
#define OUTC   128

// ---------------- scratch (device globals; no allocation) ----------------
__device__ float g_H  [NNODES * HH];      // transformed features [N,4,64]
__device__ float g_ES [NNODES * HEADS];
__device__ float g_ED [NNODES * HEADS];
__device__ float g_F1 [NNODES * HID];
__device__ float g_F2 [NNODES * HID];
__device__ int   g_DEG[NNODES];
__device__ int   g_CUR[NNODES];
__device__ int   g_ROW[NNODES + 1];
__device__ int   g_COL[ETOT];             // src node id per CSR-sorted edge

// ---------------- SIMT fp32 GEMM: C[M,Nn] = A[M,K] @ B[K,Nn] (+bias) --------
// BM=BN=128, BK=8, 256 threads, 8x8 per thread, double-buffered smem.
// Requires K % 8 == 0, Nn % 128 == 0.
__global__ __launch_bounds__(256, 2)
void sgemm128(const float* __restrict__ A, const float* __restrict__ B,
              float* __restrict__ C, int M, int Nn, int K,
              const float* __restrict__ bias) {
    const int BM = 128, BN = 128, BK = 8;
    __shared__ float As[2][BK][BM];   // transposed A tile
    __shared__ float Bs[2][BK][BN];

    int tid  = threadIdx.x;
    int brow = blockIdx.y * BM;
    int bcol = blockIdx.x * BN;
    int tr = (tid / 16) * 8;          // 0..120 step 8
    int tc = (tid % 16) * 8;

    // A tile load mapping: row = tid/2 (0..127), k-half = (tid&1)*4
    int a_row = tid >> 1;
    int a_k   = (tid & 1) * 4;
    int a_gr  = brow + a_row;
    // B tile load mapping: k-row = tid/32 (0..7), col = (tid%32)*4
    int b_kr  = tid >> 5;
    int b_c   = (tid & 31) * 4;

    const int T = K / BK;
    float acc[8][8] = {};

    // ---- load tile 0 ----
    {
        float4 va = make_float4(0.f, 0.f, 0.f, 0.f);
        if (a_gr < M) va = *reinterpret_cast<const float4*>(A + (long)a_gr * K + a_k);
        As[0][a_k + 0][a_row] = va.x;
        As[0][a_k + 1][a_row] = va.y;
        As[0][a_k + 2][a_row] = va.z;
        As[0][a_k + 3][a_row] = va.w;
        float4 vb = *reinterpret_cast<const float4*>(B + (long)b_kr * Nn + bcol + b_c);
        *reinterpret_cast<float4*>(&Bs[0][b_kr][b_c]) = vb;
    }
    __syncthreads();

    for (int t = 0; t < T; t++) {
        int cur = t & 1, nxt = cur ^ 1;
        // prefetch next tile into registers
        float4 va = make_float4(0.f, 0.f, 0.f, 0.f);
        float4 vb = make_float4(0.f, 0.f, 0.f, 0.f);
        if (t + 1 < T) {
            int k0 = (t + 1) * BK;
            if (a_gr < M) va = *reinterpret_cast<const float4*>(A + (long)a_gr * K + k0 + a_k);
            vb = *reinterpret_cast<const float4*>(B + (long)(k0 + b_kr) * Nn + bcol + b_c);
        }
        // compute on current tile
        #pragma unroll
        for (int k = 0; k < BK; k++) {
            float4 a0 = *reinterpret_cast<const float4*>(&As[cur][k][tr]);
            float4 a1 = *reinterpret_cast<const float4*>(&As[cur][k][tr + 4]);
            float4 b0 = *reinterpret_cast<const float4*>(&Bs[cur][k][tc]);
            float4 b1 = *reinterpret_cast<const float4*>(&Bs[cur][k][tc + 4]);
            float a[8] = {a0.x, a0.y, a0.z, a0.w, a1.x, a1.y, a1.z, a1.w};
            float b[8] = {b0.x, b0.y, b0.z, b0.w, b1.x, b1.y, b1.z, b1.w};
            #pragma unroll
            for (int i = 0; i < 8; i++)
                #pragma unroll
                for (int j = 0; j < 8; j++)
                    acc[i][j] += a[i] * b[j];
        }
        if (t + 1 < T) {
            As[nxt][a_k + 0][a_row] = va.x;
            As[nxt][a_k + 1][a_row] = va.y;
            As[nxt][a_k + 2][a_row] = va.z;
            As[nxt][a_k + 3][a_row] = va.w;
            *reinterpret_cast<float4*>(&Bs[nxt][b_kr][b_c]) = vb;
            __syncthreads();
        }
    }

    // ---- epilogue ----
    #pragma unroll
    for (int i = 0; i < 8; i++) {
        int gr = brow + tr + i;
        if (gr < M) {
            #pragma unroll
            for (int j4 = 0; j4 < 2; j4++) {
                float4 v;
                v.x = acc[i][j4 * 4 + 0];
                v.y = acc[i][j4 * 4 + 1];
                v.z = acc[i][j4 * 4 + 2];
                v.w = acc[i][j4 * 4 + 3];
                if (bias) {
                    v.x += bias[bcol + tc + j4 * 4 + 0];
                    v.y += bias[bcol + tc + j4 * 4 + 1];
                    v.z += bias[bcol + tc + j4 * 4 + 2];
                    v.w += bias[bcol + tc + j4 * 4 + 3];
                }
                *reinterpret_cast<float4*>(C + (long)gr * Nn + bcol + tc + j4 * 4) = v;
            }
        }
    }
}

// ---------------- per-(node,head) attention logit dots ----------------
__global__ void scores_k(const float* __restrict__ H, const float* __restrict__ asrc,
                         const float* __restrict__ adst, float* __restrict__ es,
                         float* __restrict__ ed, int NH) {
    int gw   = (blockIdx.x * blockDim.x + threadIdx.x) >> 5;
    int lane = threadIdx.x & 31;
    if (gw >= NH) return;
    int node = gw >> 2, head = gw & 3;
    const float* hp = H + (long)node * HH + head * HID;
    const float* as = asrc + head * HID;
    const float* ad = adst + head * HID;
    float h0 = hp[lane], h1 = hp[lane + 32];
    float s1 = h0 * as[lane] + h1 * as[lane + 32];
    float s2 = h0 * ad[lane] + h1 * ad[lane + 32];
    #pragma unroll
    for (int o = 16; o > 0; o >>= 1) {
        s1 += __shfl_xor_sync(0xffffffffu, s1, o);
        s2 += __shfl_xor_sync(0xffffffffu, s2, o);
    }
    if (lane == 0) { es[gw] = s1; ed[gw] = s2; }
}

// ---------------- CSR build: degree histogram ----------------
__global__ void deg_k(const int* __restrict__ ei, int* __restrict__ deg,
                      int Ein, int Etot) {
    int e = blockIdx.x * blockDim.x + threadIdx.x;
    if (e >= Etot) return;
    int d = (e < Ein) ? ei[Ein + e] : e - Ein;
    atomicAdd(&deg[d], 1);
}

// ---------------- CSR build: single-block exclusive scan ----------------
__global__ void scan_k(const int* __restrict__ deg, int* __restrict__ rowptr, int Nn) {
    __shared__ int wsum[32];
    __shared__ int carry;
    int t = threadIdx.x, lane = t & 31, wid = t >> 5;
    if (t == 0) carry = 0;
    __syncthreads();
    for (int base = 0; base < Nn; base += 1024) {
        int i = base + t;
        int v = (i < Nn) ? deg[i] : 0;
        int x = v;
        #pragma unroll
        for (int o = 1; o < 32; o <<= 1) {
            int y = __shfl_up_sync(0xffffffffu, x, o);
            if (lane >= o) x += y;
        }
        if (lane == 31) wsum[wid] = x;
        __syncthreads();
        if (wid == 0) {
            int s = wsum[lane];
            #pragma unroll
            for (int o = 1; o < 32; o <<= 1) {
                int y = __shfl_up_sync(0xffffffffu, s, o);
                if (lane >= o) s += y;
            }
            wsum[lane] = s;
        }
        __syncthreads();
        int off = carry + (wid > 0 ? wsum[wid - 1] : 0);
        if (i < Nn) rowptr[i] = off + x - v;
        int tot = wsum[31];
        __syncthreads();
        if (t == 0) carry += tot;
        __syncthreads();
    }
    if (t == 0) rowptr[Nn] = carry;
}

// ---------------- CSR build: fill column (src) lists ----------------
__global__ void fill_k(const int* __restrict__ ei, int* __restrict__ cursor,
                       const int* __restrict__ rowptr, int* __restrict__ colsrc,
                       int Ein, int Etot) {
    int e = blockIdx.x * blockDim.x + threadIdx.x;
    if (e >= Etot) return;
    int s, d;
    if (e < Ein) { s = ei[e]; d = ei[Ein + e]; }
    else         { s = d = e - Ein; }
    int p = atomicAdd(&cursor[d], 1);
    colsrc[rowptr[d] + p] = s;
}

// ---------------- fused gather: softmax aggregate + head-mean + LN + ReLU ----
__global__ void gather_k(const float* __restrict__ H, const int* __restrict__ rowptr,
                         const int* __restrict__ colsrc, const float* __restrict__ es,
                         const float* __restrict__ ed, const float* __restrict__ b,
                         const float* __restrict__ g, const float* __restrict__ be,
                         float* __restrict__ out, int Nn) {
    int warp = (blockIdx.x * blockDim.x + threadIdx.x) >> 5;
    int lane = threadIdx.x & 31;
    if (warp >= Nn) return;
    const int d  = warp;
    const int hA = lane >> 4;
    const int hB = hA + 2;

    float edv = (lane < 4) ? ed[d * 4 + lane] : 0.f;

    float4 acc1 = make_float4(0.f, 0.f, 0.f, 0.f);
    float4 acc2 = make_float4(0.f, 0.f, 0.f, 0.f);
    float denA = 0.f, denB = 0.f;

    int beg = rowptr[d], end = rowptr[d + 1];
    const float4* __restrict__ H4 = reinterpret_cast<const float4*>(H);

    int s = colsrc[beg];
    for (int e = beg; e < end; e++) {
        int s_next = (e + 1 < end) ? colsrc[e + 1] : 0;
        float w = 0.f;
        if (lane < 4) {
            float v = es[s * 4 + lane] + edv;
            v = (v > 0.f) ? v : 0.2f * v;
            w = __expf(v);
        }
        float wA = __shfl_sync(0xffffffffu, w, hA);
        float wB = __shfl_sync(0xffffffffu, w, hB);
        denA += wA; denB += wB;
        float4 h1 = H4[(long)s * 64 + lane];
        float4 h2 = H4[(long)s * 64 + lane + 32];
        acc1.x += wA * h1.x; acc1.y += wA * h1.y;
        acc1.z += wA * h1.z; acc1.w += wA * h1.w;
        acc2.x += wB * h2.x; acc2.y += wB * h2.y;
        acc2.z += wB * h2.z; acc2.w += wB * h2.w;
        s = s_next;
    }

    float rA = 1.f / denA, rB = 1.f / denB;
    float4 s4;
    s4.x = acc1.x * rA + acc2.x * rB;
    s4.y = acc1.y * rA + acc2.y * rB;
    s4.z = acc1.z * rA + acc2.z * rB;
    s4.w = acc1.w * rA + acc2.w * rB;
    s4.x += __shfl_xor_sync(0xffffffffu, s4.x, 16);
    s4.y += __shfl_xor_sync(0xffffffffu, s4.y, 16);
    s4.z += __shfl_xor_sync(0xffffffffu, s4.z, 16);
    s4.w += __shfl_xor_sync(0xffffffffu, s4.w, 16);

    int ch = (lane & 15) * 4;
    s4.x = s4.x * 0.25f + b[ch + 0];
    s4.y = s4.y * 0.25f + b[ch + 1];
    s4.z = s4.z * 0.25f + b[ch + 2];
    s4.w = s4.w * 0.25f + b[ch + 3];

    float sum = s4.x + s4.y + s4.z + s4.w;
    float ssq = s4.x * s4.x + s4.y * s4.y + s4.z * s4.z + s4.w * s4.w;
    #pragma unroll
    for (int o = 16; o > 0; o >>= 1) {
        sum += __shfl_xor_sync(0xffffffffu, sum, o);
        ssq += __shfl_xor_sync(0xffffffffu, ssq, o);
    }
    float mean = sum * (1.f / 128.f);
    float var  = ssq * (1.f / 128.f) - mean * mean;
    float inv  = rsqrtf(var + 1e-5f);

    s4.x = fmaxf((s4.x - mean) * inv * g[ch + 0] + be[ch + 0], 0.f);
    s4.y = fmaxf((s4.y - mean) * inv * g[ch + 1] + be[ch + 1], 0.f);
    s4.z = fmaxf((s4.z - mean) * inv * g[ch + 2] + be[ch + 2], 0.f);
    s4.w = fmaxf((s4.w - mean) * inv * g[ch + 3] + be[ch + 3], 0.f);

    if (lane < 16)
        reinterpret_cast<float4*>(out + (long)d * HID)[lane] = s4;
}

// ---------------------------------------------------------------------------
extern "C" void kernel_launch(void* const* d_in, const int* in_sizes, int n_in,
                              void* d_out, int out_size) {
    const float* x     = (const float*)d_in[0];
    const int*   ei    = (const int*)  d_in[1];
    const float* W1    = (const float*)d_in[2];
    const float* asrc1 = (const float*)d_in[3];
    const float* adst1 = (const float*)d_in[4];
    const float* b1    = (const float*)d_in[5];
    const float* g1    = (const float*)d_in[6];
    const float* be1   = (const float*)d_in[7];
    const float* W2    = (const float*)d_in[8];
    const float* asrc2 = (const float*)d_in[9];
    const float* adst2 = (const float*)d_in[10];
    const float* b2    = (const float*)d_in[11];
    const float* g2    = (const float*)d_in[12];
    const float* be2   = (const float*)d_in[13];
    const float* Wo    = (const float*)d_in[14];
    const float* bo    = (const float*)d_in[15];
    float* out = (float*)d_out;

    const int Nn   = in_sizes[0] / INC;      // 50000
    const int Ein  = in_sizes[1] / 2;        // 800000
    const int Etot = Ein + Nn;               // 850000
    const int NH   = Nn * HEADS;

    float *H, *ES, *ED, *F1, *F2;
    int *DEG, *CUR, *ROW, *COL;
    cudaGetSymbolAddress((void**)&H,   g_H);
    cudaGetSymbolAddress((void**)&ES,  g_ES);
    cudaGetSymbolAddress((void**)&ED,  g_ED);
    cudaGetSymbolAddress((void**)&F1,  g_F1);
    cudaGetSymbolAddress((void**)&F2,  g_F2);
    cudaGetSymbolAddress((void**)&DEG, g_DEG);
    cudaGetSymbolAddress((void**)&CUR, g_CUR);
    cudaGetSymbolAddress((void**)&ROW, g_ROW);
    cudaGetSymbolAddress((void**)&COL, g_COL);

    dim3 gemm1_grid(HH / 128, (Nn + 127) / 128);     // x@W1  -> H
    dim3 gemm2_grid(HH / 128, (Nn + 127) / 128);     // F1@W2 -> H
    dim3 gemmo_grid(OUTC / 128, (Nn + 127) / 128);   // F2@Wo -> out

    int score_blocks = (NH * 32 + 255) / 256;
    int edge_blocks  = (Etot + 255) / 256;
    int node_warpblk = (Nn * 32 + 255) / 256;

    // ---------------- CSR build (shared by both layers) ----------------
    cudaMemsetAsync(DEG, 0, (size_t)Nn * sizeof(int), 0);
    cudaMemsetAsync(CUR, 0, (size_t)Nn * sizeof(int), 0);
    deg_k<<<edge_blocks, 256>>>(ei, DEG, Ein, Etot);
    scan_k<<<1, 1024>>>(DEG, ROW, Nn);
    fill_k<<<edge_blocks, 256>>>(ei, CUR, ROW, COL, Ein, Etot);

    // ---------------- layer 1 ----------------
    sgemm128<<<gemm1_grid, 256>>>(x, W1, H, Nn, HH, INC, nullptr);
    scores_k<<<score_blocks, 256>>>(H, asrc1, adst1, ES, ED, NH);
    gather_k<<<node_warpblk, 256>>>(H, ROW, COL, ES, ED, b1, g1, be1, F1, Nn);

    // ---------------- layer 2 ----------------
    sgemm128<<<gemm2_grid, 256>>>(F1, W2, H, Nn, HH, HID, nullptr);
    scores_k<<<score_blocks, 256>>>(H, asrc2, adst2, ES, ED, NH);
    gather_k<<<node_warpblk, 256>>>(H, ROW, COL, ES, ED, b2, g2, be2, F2, Nn);

    // ---------------- output projection ----------------
    sgemm128<<<gemmo_grid, 256>>>(F2, Wo, out, Nn, OUTC, HID, bo);
}

// round 4
// speedup vs baseline: 2.4693x; 1.1003x over previous
#include <cuda_runtime.h>
#include <cuda_bf16.h>

#define NNODES 50000
#define NEDGES 800000
#define ETOT   (NNODES + NEDGES)
#define HEADS  4
#define HID    64
#define HH     256   // HEADS*HID
#define INC    128
#define OUTC   128
#define NCHUNK ((NNODES + 1023) / 1024)

// ---------------- scratch (device globals; no allocation) ----------------
__device__ float g_H  [NNODES * HH];
__device__ float g_ES [NNODES * HEADS];
__device__ float g_ED [NNODES * HEADS];
__device__ float g_F1 [NNODES * HID];
__device__ float g_F2 [NNODES * HID];
__device__ int   g_DEG[NNODES];
__device__ int   g_CUR[NNODES];
__device__ int   g_ROW[NNODES + 1];
__device__ int   g_COL[ETOT];
__device__ int   g_CSUM[NCHUNK + 1];

// ---------------- SIMT fp32 GEMM: C[M,Nn] = A[M,K] @ B[K,Nn] (+bias) --------
// BM=BN=128, BK=8, 256 threads, 8x8 per thread (split-column mapping),
// double-buffered smem, conflict-free LDS. K % 8 == 0, Nn % 128 == 0.
__global__ __launch_bounds__(256, 2)
void sgemm128(const float* __restrict__ A, const float* __restrict__ B,
              float* __restrict__ C, int M, int Nn, int K,
              const float* __restrict__ bias) {
    const int BM = 128, BN = 128, BK = 8;
    __shared__ float As[2][BK][BM + 4];   // +4 pad: conflict-free STS transpose
    __shared__ float Bs[2][BK][BN];

    int tid  = threadIdx.x;
    int brow = blockIdx.y * BM;
    int bcol = blockIdx.x * BN;
    int w    = tid >> 5, lane = tid & 31;
    int wm   = w & 3,  wn = w >> 2;       // 4 warps along M, 2 along N
    int mg   = lane >> 3, ng = lane & 7;  // 4x8 lanes
    int tr   = wm * 32 + mg * 8;          // 8 rows per thread
    int tc0  = wn * 64 + ng * 4;          // cols tc0..+3 and tc0+32..+35

    int a_row = tid >> 1, a_k = (tid & 1) * 4, a_gr = brow + a_row;
    int b_kr  = tid >> 5, b_c = (tid & 31) * 4;

    const int T = K / BK;
    float acc[8][8] = {};

    // ---- load tile 0 ----
    {
        float4 va = make_float4(0.f, 0.f, 0.f, 0.f);
        if (a_gr < M) va = *reinterpret_cast<const float4*>(A + (long)a_gr * K + a_k);
        As[0][a_k + 0][a_row] = va.x;
        As[0][a_k + 1][a_row] = va.y;
        As[0][a_k + 2][a_row] = va.z;
        As[0][a_k + 3][a_row] = va.w;
        float4 vb = *reinterpret_cast<const float4*>(B + (long)b_kr * Nn + bcol + b_c);
        *reinterpret_cast<float4*>(&Bs[0][b_kr][b_c]) = vb;
    }
    __syncthreads();

    for (int t = 0; t < T; t++) {
        int cur = t & 1, nxt = cur ^ 1;
        float4 va = make_float4(0.f, 0.f, 0.f, 0.f);
        float4 vb = make_float4(0.f, 0.f, 0.f, 0.f);
        if (t + 1 < T) {
            int k0 = (t + 1) * BK;
            if (a_gr < M) va = *reinterpret_cast<const float4*>(A + (long)a_gr * K + k0 + a_k);
            vb = *reinterpret_cast<const float4*>(B + (long)(k0 + b_kr) * Nn + bcol + b_c);
        }
        #pragma unroll
        for (int k = 0; k < BK; k++) {
            float4 a0 = *reinterpret_cast<const float4*>(&As[cur][k][tr]);
            float4 a1 = *reinterpret_cast<const float4*>(&As[cur][k][tr + 4]);
            float4 b0 = *reinterpret_cast<const float4*>(&Bs[cur][k][tc0]);
            float4 b1 = *reinterpret_cast<const float4*>(&Bs[cur][k][tc0 + 32]);
            float a[8] = {a0.x, a0.y, a0.z, a0.w, a1.x, a1.y, a1.z, a1.w};
            float b[8] = {b0.x, b0.y, b0.z, b0.w, b1.x, b1.y, b1.z, b1.w};
            #pragma unroll
            for (int i = 0; i < 8; i++)
                #pragma unroll
                for (int j = 0; j < 8; j++)
                    acc[i][j] += a[i] * b[j];
        }
        if (t + 1 < T) {
            As[nxt][a_k + 0][a_row] = va.x;
            As[nxt][a_k + 1][a_row] = va.y;
            As[nxt][a_k + 2][a_row] = va.z;
            As[nxt][a_k + 3][a_row] = va.w;
            *reinterpret_cast<float4*>(&Bs[nxt][b_kr][b_c]) = vb;
            __syncthreads();
        }
    }

    // ---- epilogue: two float4 stores per row ----
    #pragma unroll
    for (int i = 0; i < 8; i++) {
        int gr = brow + tr + i;
        if (gr < M) {
            float4 v0, v1;
            v0.x = acc[i][0]; v0.y = acc[i][1]; v0.z = acc[i][2]; v0.w = acc[i][3];
            v1.x = acc[i][4]; v1.y = acc[i][5]; v1.z = acc[i][6]; v1.w = acc[i][7];
            if (bias) {
                v0.x += bias[bcol + tc0 + 0];  v0.y += bias[bcol + tc0 + 1];
                v0.z += bias[bcol + tc0 + 2];  v0.w += bias[bcol + tc0 + 3];
                v1.x += bias[bcol + tc0 + 32]; v1.y += bias[bcol + tc0 + 33];
                v1.z += bias[bcol + tc0 + 34]; v1.w += bias[bcol + tc0 + 35];
            }
            *reinterpret_cast<float4*>(C + (long)gr * Nn + bcol + tc0)      = v0;
            *reinterpret_cast<float4*>(C + (long)gr * Nn + bcol + tc0 + 32) = v1;
        }
    }
}

// ---------------- per-(node,head) attention logit dots ----------------
__global__ void scores_k(const float* __restrict__ H, const float* __restrict__ asrc,
                         const float* __restrict__ adst, float* __restrict__ es,
                         float* __restrict__ ed, int NH) {
    int gw   = (blockIdx.x * blockDim.x + threadIdx.x) >> 5;
    int lane = threadIdx.x & 31;
    if (gw >= NH) return;
    int node = gw >> 2, head = gw & 3;
    const float* hp = H + (long)node * HH + head * HID;
    const float* as = asrc + head * HID;
    const float* ad = adst + head * HID;
    float h0 = hp[lane], h1 = hp[lane + 32];
    float s1 = h0 * as[lane] + h1 * as[lane + 32];
    float s2 = h0 * ad[lane] + h1 * ad[lane + 32];
    #pragma unroll
    for (int o = 16; o > 0; o >>= 1) {
        s1 += __shfl_xor_sync(0xffffffffu, s1, o);
        s2 += __shfl_xor_sync(0xffffffffu, s2, o);
    }
    if (lane == 0) { es[gw] = s1; ed[gw] = s2; }
}

// ---------------- CSR build ----------------
__global__ void deg_k(const int* __restrict__ ei, int* __restrict__ deg,
                      int Ein, int Etot) {
    int e = blockIdx.x * blockDim.x + threadIdx.x;
    if (e >= Etot) return;
    int d = (e < Ein) ? ei[Ein + e] : e - Ein;
    atomicAdd(&deg[d], 1);
}

// chunk sums: one 1024-thread block per 1024-element chunk
__global__ void chunksum_k(const int* __restrict__ deg, int* __restrict__ csum, int Nn) {
    __shared__ int wsum[32];
    int t = threadIdx.x, lane = t & 31, wid = t >> 5;
    int i = blockIdx.x * 1024 + t;
    int v = (i < Nn) ? deg[i] : 0;
    #pragma unroll
    for (int o = 16; o > 0; o >>= 1) v += __shfl_xor_sync(0xffffffffu, v, o);
    if (lane == 0) wsum[wid] = v;
    __syncthreads();
    if (wid == 0) {
        int s = wsum[lane];
        #pragma unroll
        for (int o = 16; o > 0; o >>= 1) s += __shfl_xor_sync(0xffffffffu, s, o);
        if (lane == 0) csum[blockIdx.x] = s;
    }
}

// tiny serial exclusive scan over chunk sums (nchunk ~ 49)
__global__ void scanchunks_k(int* __restrict__ csum, int* __restrict__ rowptr,
                             int nchunk, int Nn) {
    int run = 0;
    for (int i = 0; i < nchunk; i++) { int v = csum[i]; csum[i] = run; run += v; }
    csum[nchunk] = run;
    rowptr[Nn] = run;
}

// per-chunk exclusive scan + chunk offset -> rowptr
__global__ void rowptr_k(const int* __restrict__ deg, const int* __restrict__ csum,
                         int* __restrict__ rowptr, int Nn) {
    __shared__ int wsum[32];
    int t = threadIdx.x, lane = t & 31, wid = t >> 5;
    int i = blockIdx.x * 1024 + t;
    int v = (i < Nn) ? deg[i] : 0;
    int x = v;
    #pragma unroll
    for (int o = 1; o < 32; o <<= 1) {
        int y = __shfl_up_sync(0xffffffffu, x, o);
        if (lane >= o) x += y;
    }
    if (lane == 31) wsum[wid] = x;
    __syncthreads();
    if (wid == 0) {
        int s = wsum[lane];
        #pragma unroll
        for (int o = 1; o < 32; o <<= 1) {
            int y = __shfl_up_sync(0xffffffffu, s, o);
            if (lane >= o) s += y;
        }
        wsum[lane] = s;
    }
    __syncthreads();
    int off = csum[blockIdx.x] + (wid > 0 ? wsum[wid - 1] : 0);
    if (i < Nn) rowptr[i] = off + x - v;
}

__global__ void fill_k(const int* __restrict__ ei, int* __restrict__ cursor,
                       const int* __restrict__ rowptr, int* __restrict__ colsrc,
                       int Ein, int Etot) {
    int e = blockIdx.x * blockDim.x + threadIdx.x;
    if (e >= Etot) return;
    int s, d;
    if (e < Ein) { s = ei[e]; d = ei[Ein + e]; }
    else         { s = d = e - Ein; }
    int p = atomicAdd(&cursor[d], 1);
    colsrc[rowptr[d] + p] = s;
}

// ---------------- fused gather (unroll-2): softmax aggregate + head-mean
// + bias + LayerNorm + ReLU.  One warp per destination node. ----------------
__global__ void gather_k(const float* __restrict__ H, const int* __restrict__ rowptr,
                         const int* __restrict__ colsrc, const float* __restrict__ es,
                         const float* __restrict__ ed, const float* __restrict__ b,
                         const float* __restrict__ g, const float* __restrict__ be,
                         float* __restrict__ out, int Nn) {
    int warp = (blockIdx.x * blockDim.x + threadIdx.x) >> 5;
    int lane = threadIdx.x & 31;
    if (warp >= Nn) return;
    const int d  = warp;
    const int hA = lane >> 4;
    const int hB = hA + 2;

    float edv = (lane < 4) ? ed[d * 4 + lane] : 0.f;

    float4 p1a = make_float4(0.f,0.f,0.f,0.f), p2a = make_float4(0.f,0.f,0.f,0.f);
    float4 p1b = make_float4(0.f,0.f,0.f,0.f), p2b = make_float4(0.f,0.f,0.f,0.f);
    float dA0 = 0.f, dB0 = 0.f, dA1 = 0.f, dB1 = 0.f;

    int beg = rowptr[d], end = rowptr[d + 1];
    const float4* __restrict__ H4 = reinterpret_cast<const float4*>(H);

    int e = beg;
    for (; e + 2 <= end; e += 2) {
        int s0 = colsrc[e], s1 = colsrc[e + 1];
        float w0 = 0.f, w1 = 0.f;
        if (lane < 4) {
            float v0 = es[s0 * 4 + lane] + edv;
            v0 = (v0 > 0.f) ? v0 : 0.2f * v0;
            float v1 = es[s1 * 4 + lane] + edv;
            v1 = (v1 > 0.f) ? v1 : 0.2f * v1;
            w0 = __expf(v0); w1 = __expf(v1);
        }
        float wA0 = __shfl_sync(0xffffffffu, w0, hA);
        float wB0 = __shfl_sync(0xffffffffu, w0, hB);
        float wA1 = __shfl_sync(0xffffffffu, w1, hA);
        float wB1 = __shfl_sync(0xffffffffu, w1, hB);
        float4 h10 = H4[(long)s0 * 64 + lane];
        float4 h20 = H4[(long)s0 * 64 + lane + 32];
        float4 h11 = H4[(long)s1 * 64 + lane];
        float4 h21 = H4[(long)s1 * 64 + lane + 32];
        dA0 += wA0; dB0 += wB0; dA1 += wA1; dB1 += wB1;
        p1a.x += wA0 * h10.x; p1a.y += wA0 * h10.y; p1a.z += wA0 * h10.z; p1a.w += wA0 * h10.w;
        p2a.x += wB0 * h20.x; p2a.y += wB0 * h20.y; p2a.z += wB0 * h20.z; p2a.w += wB0 * h20.w;
        p1b.x += wA1 * h11.x; p1b.y += wA1 * h11.y; p1b.z += wA1 * h11.z; p1b.w += wA1 * h11.w;
        p2b.x += wB1 * h21.x; p2b.y += wB1 * h21.y; p2b.z += wB1 * h21.z; p2b.w += wB1 * h21.w;
    }
    if (e < end) {
        int s0 = colsrc[e];
        float w0 = 0.f;
        if (lane < 4) {
            float v0 = es[s0 * 4 + lane] + edv;
            v0 = (v0 > 0.f) ? v0 : 0.2f * v0;
            w0 = __expf(v0);
        }
        float wA0 = __shfl_sync(0xffffffffu, w0, hA);
        float wB0 = __shfl_sync(0xffffffffu, w0, hB);
        float4 h10 = H4[(long)s0 * 64 + lane];
        float4 h20 = H4[(long)s0 * 64 + lane + 32];
        dA0 += wA0; dB0 += wB0;
        p1a.x += wA0 * h10.x; p1a.y += wA0 * h10.y; p1a.z += wA0 * h10.z; p1a.w += wA0 * h10.w;
        p2a.x += wB0 * h20.x; p2a.y += wB0 * h20.y; p2a.z += wB0 * h20.z; p2a.w += wB0 * h20.w;
    }

    // merge unroll copies
    float denA = dA0 + dA1, denB = dB0 + dB1;
    float4 acc1, acc2;
    acc1.x = p1a.x + p1b.x; acc1.y = p1a.y + p1b.y;
    acc1.z = p1a.z + p1b.z; acc1.w = p1a.w + p1b.w;
    acc2.x = p2a.x + p2b.x; acc2.y = p2a.y + p2b.y;
    acc2.z = p2a.z + p2b.z; acc2.w = p2a.w + p2b.w;

    float rA = 1.f / denA, rB = 1.f / denB;
    float4 s4;
    s4.x = acc1.x * rA + acc2.x * rB;
    s4.y = acc1.y * rA + acc2.y * rB;
    s4.z = acc1.z * rA + acc2.z * rB;
    s4.w = acc1.w * rA + acc2.w * rB;
    s4.x += __shfl_xor_sync(0xffffffffu, s4.x, 16);
    s4.y += __shfl_xor_sync(0xffffffffu, s4.y, 16);
    s4.z += __shfl_xor_sync(0xffffffffu, s4.z, 16);
    s4.w += __shfl_xor_sync(0xffffffffu, s4.w, 16);

    int ch = (lane & 15) * 4;
    s4.x = s4.x * 0.25f + b[ch + 0];
    s4.y = s4.y * 0.25f + b[ch + 1];
    s4.z = s4.z * 0.25f + b[ch + 2];
    s4.w = s4.w * 0.25f + b[ch + 3];

    float sum = s4.x + s4.y + s4.z + s4.w;
    float ssq = s4.x * s4.x + s4.y * s4.y + s4.z * s4.z + s4.w * s4.w;
    #pragma unroll
    for (int o = 16; o > 0; o >>= 1) {
        sum += __shfl_xor_sync(0xffffffffu, sum, o);
        ssq += __shfl_xor_sync(0xffffffffu, ssq, o);
    }
    float mean = sum * (1.f / 128.f);
    float var  = ssq * (1.f / 128.f) - mean * mean;
    float inv  = rsqrtf(var + 1e-5f);

    s4.x = fmaxf((s4.x - mean) * inv * g[ch + 0] + be[ch + 0], 0.f);
    s4.y = fmaxf((s4.y - mean) * inv * g[ch + 1] + be[ch + 1], 0.f);
    s4.z = fmaxf((s4.z - mean) * inv * g[ch + 2] + be[ch + 2], 0.f);
    s4.w = fmaxf((s4.w - mean) * inv * g[ch + 3] + be[ch + 3], 0.f);

    if (lane < 16)
        reinterpret_cast<float4*>(out + (long)d * HID)[lane] = s4;
}

// ---------------------------------------------------------------------------
extern "C" void kernel_launch(void* const* d_in, const int* in_sizes, int n_in,
                              void* d_out, int out_size) {
    const float* x     = (const float*)d_in[0];
    const int*   ei    = (const int*)  d_in[1];
    const float* W1    = (const float*)d_in[2];
    const float* asrc1 = (const float*)d_in[3];
    const float* adst1 = (const float*)d_in[4];
    const float* b1    = (const float*)d_in[5];
    const float* g1    = (const float*)d_in[6];
    const float* be1   = (const float*)d_in[7];
    const float* W2    = (const float*)d_in[8];
    const float* asrc2 = (const float*)d_in[9];
    const float* adst2 = (const float*)d_in[10];
    const float* b2    = (const float*)d_in[11];
    const float* g2    = (const float*)d_in[12];
    const float* be2   = (const float*)d_in[13];
    const float* Wo    = (const float*)d_in[14];
    const float* bo    = (const float*)d_in[15];
    float* out = (float*)d_out;

    const int Nn   = in_sizes[0] / INC;      // 50000
    const int Ein  = in_sizes[1] / 2;        // 800000
    const int Etot = Ein + Nn;               // 850000
    const int NH   = Nn * HEADS;
    const int nchunk = (Nn + 1023) / 1024;

    float *H, *ES, *ED, *F1, *F2;
    int *DEG, *CUR, *ROW, *COL, *CSUM;
    cudaGetSymbolAddress((void**)&H,    g_H);
    cudaGetSymbolAddress((void**)&ES,   g_ES);
    cudaGetSymbolAddress((void**)&ED,   g_ED);
    cudaGetSymbolAddress((void**)&F1,   g_F1);
    cudaGetSymbolAddress((void**)&F2,   g_F2);
    cudaGetSymbolAddress((void**)&DEG,  g_DEG);
    cudaGetSymbolAddress((void**)&CUR,  g_CUR);
    cudaGetSymbolAddress((void**)&ROW,  g_ROW);
    cudaGetSymbolAddress((void**)&COL,  g_COL);
    cudaGetSymbolAddress((void**)&CSUM, g_CSUM);

    dim3 gemm1_grid(HH / 128, (Nn + 127) / 128);
    dim3 gemm2_grid(HH / 128, (Nn + 127) / 128);
    dim3 gemmo_grid(OUTC / 128, (Nn + 127) / 128);

    int score_blocks = (NH * 32 + 255) / 256;
    int edge_blocks  = (Etot + 255) / 256;
    int node_warpblk = (Nn * 32 + 255) / 256;

    // ---------------- CSR build (shared by both layers) ----------------
    cudaMemsetAsync(DEG, 0, (size_t)Nn * sizeof(int), 0);
    cudaMemsetAsync(CUR, 0, (size_t)Nn * sizeof(int), 0);
    deg_k<<<edge_blocks, 256>>>(ei, DEG, Ein, Etot);
    chunksum_k<<<nchunk, 1024>>>(DEG, CSUM, Nn);
    scanchunks_k<<<1, 1>>>(CSUM, ROW, nchunk, Nn);
    rowptr_k<<<nchunk, 1024>>>(DEG, CSUM, ROW, Nn);
    fill_k<<<edge_blocks, 256>>>(ei, CUR, ROW, COL, Ein, Etot);

    // ---------------- layer 1 ----------------
    sgemm128<<<gemm1_grid, 256>>>(x, W1, H, Nn, HH, INC, nullptr);
    scores_k<<<score_blocks, 256>>>(H, asrc1, adst1, ES, ED, NH);
    gather_k<<<node_warpblk, 256>>>(H, ROW, COL, ES, ED, b1, g1, be1, F1, Nn);

    // ---------------- layer 2 ----------------
    sgemm128<<<gemm2_grid, 256>>>(F1, W2, H, Nn, HH, HID, nullptr);
    scores_k<<<score_blocks, 256>>>(H, asrc2, adst2, ES, ED, NH);
    gather_k<<<node_warpblk, 256>>>(H, ROW, COL, ES, ED, b2, g2, be2, F2, Nn);

    // ---------------- output projection ----------------
    sgemm128<<<gemmo_grid, 256>>>(F2, Wo, out, Nn, OUTC, HID, bo);
}

// round 5
// speedup vs baseline: 2.7157x; 1.0998x over previous
#include <cuda_runtime.h>
#include <cuda_bf16.h>
#include <cstdint>

#define NNODES 50000
#define NEDGES 800000
#define ETOT   (NNODES + NEDGES)
#define HEADS  4
#define HID    64
#define HH     256   // HEADS*HID
#define INC    128
#define OUTC   128
#define NCHUNK ((NNODES + 1023) / 1024)

// ---------------- scratch (device globals; no allocation) ----------------
__device__ float g_H  [NNODES * HH];
__device__ float g_ES [NNODES * HEADS];
__device__ float g_ED [NNODES * HEADS];
__device__ float g_F1 [NNODES * HID];
__device__ float g_F2 [NNODES * HID];
__device__ int   g_DEG[NNODES];
__device__ int   g_CUR[NNODES];
__device__ int   g_ROW[NNODES + 1];
__device__ int   g_COL[ETOT];
__device__ int   g_CSUM[NCHUNK + 1];

// ---------------- helpers ----------------
__device__ __forceinline__ uint32_t f2tf32(float f) {
    uint32_t u;
    asm("cvt.rna.tf32.f32 %0, %1;" : "=r"(u) : "f"(f));
    return u;
}

__device__ __forceinline__ void mma_tf32(float* c, const uint32_t* a, const uint32_t* b) {
    asm volatile(
        "mma.sync.aligned.m16n8k8.row.col.f32.tf32.tf32.f32 "
        "{%0,%1,%2,%3}, {%4,%5,%6,%7}, {%8,%9}, {%0,%1,%2,%3};\n"
        : "+f"(c[0]), "+f"(c[1]), "+f"(c[2]), "+f"(c[3])
        : "r"(a[0]), "r"(a[1]), "r"(a[2]), "r"(a[3]), "r"(b[0]), "r"(b[1]));
}

// ---------------- TF32 tensor-core GEMM: C[M,Nn]=A[M,K]@B[K,Nn] (+bias) -----
// BM=BN=128, BK=16, 256 threads (8 warps, 2Mx4N), warp tile 64x32,
// double-buffered smem, conflict-free fragment LDS. K%16==0, Nn%128==0.
#define ALD 20    // A smem row stride (16 + 4 pad): frag banks g*20+tg distinct
#define BLD 136   // B smem row stride (128 + 8 pad): frag banks tg*8+g distinct

__global__ __launch_bounds__(256, 2)
void tgemm128(const float* __restrict__ A, const float* __restrict__ B,
              float* __restrict__ C, int M, int Nn, int K,
              const float* __restrict__ bias) {
    const int BM = 128, BK = 16;
    __shared__ uint32_t As[2][BM * ALD];   // [row][k]
    __shared__ uint32_t Bs[2][BK * BLD];   // [k][n]

    int tid  = threadIdx.x;
    int brow = blockIdx.y * BM;
    int bcol = blockIdx.x * 128;
    int w    = tid >> 5, lane = tid & 31;
    int wm   = w & 1, wn = w >> 1;           // 2 warps on M, 4 on N
    int g    = lane >> 2, tg = lane & 3;     // fragment group / thread-in-group

    // global->smem load mapping
    int ar = tid >> 2, ac = (tid & 3) * 4;   // A: rows ar, ar+64; cols ac..ac+3
    int br = tid >> 5, bc = (tid & 31) * 4;  // B: rows br, br+8;  cols bc..bc+3

    const int T = K / BK;
    float acc[4][4][4];
    #pragma unroll
    for (int i = 0; i < 4; i++)
        #pragma unroll
        for (int j = 0; j < 4; j++)
            #pragma unroll
            for (int r = 0; r < 4; r++) acc[i][j][r] = 0.f;

    // ---- load tile 0 ----
    {
        float4 va0 = make_float4(0.f,0.f,0.f,0.f), va1 = va0;
        long r0 = brow + ar, r1 = brow + ar + 64;
        if (r0 < M) va0 = *reinterpret_cast<const float4*>(A + r0 * K + ac);
        if (r1 < M) va1 = *reinterpret_cast<const float4*>(A + r1 * K + ac);
        uint32_t* d0 = &As[0][ar * ALD + ac];
        d0[0]=f2tf32(va0.x); d0[1]=f2tf32(va0.y); d0[2]=f2tf32(va0.z); d0[3]=f2tf32(va0.w);
        uint32_t* d1 = &As[0][(ar + 64) * ALD + ac];
        d1[0]=f2tf32(va1.x); d1[1]=f2tf32(va1.y); d1[2]=f2tf32(va1.z); d1[3]=f2tf32(va1.w);
        float4 vb0 = *reinterpret_cast<const float4*>(B + (long)br * Nn + bcol + bc);
        float4 vb1 = *reinterpret_cast<const float4*>(B + (long)(br + 8) * Nn + bcol + bc);
        uint32_t* e0 = &Bs[0][br * BLD + bc];
        e0[0]=f2tf32(vb0.x); e0[1]=f2tf32(vb0.y); e0[2]=f2tf32(vb0.z); e0[3]=f2tf32(vb0.w);
        uint32_t* e1 = &Bs[0][(br + 8) * BLD + bc];
        e1[0]=f2tf32(vb1.x); e1[1]=f2tf32(vb1.y); e1[2]=f2tf32(vb1.z); e1[3]=f2tf32(vb1.w);
    }
    __syncthreads();

    for (int t = 0; t < T; t++) {
        int buf = t & 1;
        // prefetch next tile into registers
        float4 va0 = make_float4(0.f,0.f,0.f,0.f), va1 = va0, vb0 = va0, vb1 = va0;
        if (t + 1 < T) {
            int k0 = (t + 1) * BK;
            long r0 = brow + ar, r1 = brow + ar + 64;
            if (r0 < M) va0 = *reinterpret_cast<const float4*>(A + r0 * K + k0 + ac);
            if (r1 < M) va1 = *reinterpret_cast<const float4*>(A + r1 * K + k0 + ac);
            vb0 = *reinterpret_cast<const float4*>(B + (long)(k0 + br) * Nn + bcol + bc);
            vb1 = *reinterpret_cast<const float4*>(B + (long)(k0 + br + 8) * Nn + bcol + bc);
        }
        // compute: 2 k-substeps of 8
        #pragma unroll
        for (int kk = 0; kk < BK; kk += 8) {
            uint32_t af[4][4];
            #pragma unroll
            for (int mt = 0; mt < 4; mt++) {
                int r0 = (wm * 64 + mt * 16 + g) * ALD + kk + tg;
                af[mt][0] = As[buf][r0];
                af[mt][1] = As[buf][r0 + 8 * ALD];
                af[mt][2] = As[buf][r0 + 4];
                af[mt][3] = As[buf][r0 + 8 * ALD + 4];
            }
            uint32_t bf[4][2];
            #pragma unroll
            for (int nt = 0; nt < 4; nt++) {
                int c0 = wn * 32 + nt * 8 + g;
                bf[nt][0] = Bs[buf][(kk + tg) * BLD + c0];
                bf[nt][1] = Bs[buf][(kk + tg + 4) * BLD + c0];
            }
            #pragma unroll
            for (int mt = 0; mt < 4; mt++)
                #pragma unroll
                for (int nt = 0; nt < 4; nt++)
                    mma_tf32(acc[mt][nt], af[mt], bf[nt]);
        }
        if (t + 1 < T) {
            int nb = buf ^ 1;
            uint32_t* d0 = &As[nb][ar * ALD + ac];
            d0[0]=f2tf32(va0.x); d0[1]=f2tf32(va0.y); d0[2]=f2tf32(va0.z); d0[3]=f2tf32(va0.w);
            uint32_t* d1 = &As[nb][(ar + 64) * ALD + ac];
            d1[0]=f2tf32(va1.x); d1[1]=f2tf32(va1.y); d1[2]=f2tf32(va1.z); d1[3]=f2tf32(va1.w);
            uint32_t* e0 = &Bs[nb][br * BLD + bc];
            e0[0]=f2tf32(vb0.x); e0[1]=f2tf32(vb0.y); e0[2]=f2tf32(vb0.z); e0[3]=f2tf32(vb0.w);
            uint32_t* e1 = &Bs[nb][(br + 8) * BLD + bc];
            e1[0]=f2tf32(vb1.x); e1[1]=f2tf32(vb1.y); e1[2]=f2tf32(vb1.z); e1[3]=f2tf32(vb1.w);
            __syncthreads();
        }
    }

    // ---- epilogue ----
    #pragma unroll
    for (int mt = 0; mt < 4; mt++) {
        #pragma unroll
        for (int nt = 0; nt < 4; nt++) {
            int r = brow + wm * 64 + mt * 16 + g;
            int c = bcol + wn * 32 + nt * 8 + tg * 2;
            float bx = 0.f, by = 0.f;
            if (bias) { bx = bias[c]; by = bias[c + 1]; }
            if (r < M) {
                float2 v = make_float2(acc[mt][nt][0] + bx, acc[mt][nt][1] + by);
                *reinterpret_cast<float2*>(C + (long)r * Nn + c) = v;
            }
            if (r + 8 < M) {
                float2 v = make_float2(acc[mt][nt][2] + bx, acc[mt][nt][3] + by);
                *reinterpret_cast<float2*>(C + (long)(r + 8) * Nn + c) = v;
            }
        }
    }
}

// ---------------- per-(node,head) attention logit dots ----------------
__global__ void scores_k(const float* __restrict__ H, const float* __restrict__ asrc,
                         const float* __restrict__ adst, float* __restrict__ es,
                         float* __restrict__ ed, int NH) {
    int gw   = (blockIdx.x * blockDim.x + threadIdx.x) >> 5;
    int lane = threadIdx.x & 31;
    if (gw >= NH) return;
    int node = gw >> 2, head = gw & 3;
    const float* hp = H + (long)node * HH + head * HID;
    const float* as = asrc + head * HID;
    const float* ad = adst + head * HID;
    float h0 = hp[lane], h1 = hp[lane + 32];
    float s1 = h0 * as[lane] + h1 * as[lane + 32];
    float s2 = h0 * ad[lane] + h1 * ad[lane + 32];
    #pragma unroll
    for (int o = 16; o > 0; o >>= 1) {
        s1 += __shfl_xor_sync(0xffffffffu, s1, o);
        s2 += __shfl_xor_sync(0xffffffffu, s2, o);
    }
    if (lane == 0) { es[gw] = s1; ed[gw] = s2; }
}

// ---------------- CSR build ----------------
__global__ void deg_k(const int* __restrict__ ei, int* __restrict__ deg,
                      int Ein, int Etot) {
    int e = blockIdx.x * blockDim.x + threadIdx.x;
    if (e >= Etot) return;
    int d = (e < Ein) ? ei[Ein + e] : e - Ein;
    atomicAdd(&deg[d], 1);
}

__global__ void chunksum_k(const int* __restrict__ deg, int* __restrict__ csum, int Nn) {
    __shared__ int wsum[32];
    int t = threadIdx.x, lane = t & 31, wid = t >> 5;
    int i = blockIdx.x * 1024 + t;
    int v = (i < Nn) ? deg[i] : 0;
    #pragma unroll
    for (int o = 16; o > 0; o >>= 1) v += __shfl_xor_sync(0xffffffffu, v, o);
    if (lane == 0) wsum[wid] = v;
    __syncthreads();
    if (wid == 0) {
        int s = wsum[lane];
        #pragma unroll
        for (int o = 16; o > 0; o >>= 1) s += __shfl_xor_sync(0xffffffffu, s, o);
        if (lane == 0) csum[blockIdx.x] = s;
    }
}

__global__ void scanchunks_k(int* __restrict__ csum, int* __restrict__ rowptr,
                             int nchunk, int Nn) {
    int run = 0;
    for (int i = 0; i < nchunk; i++) { int v = csum[i]; csum[i] = run; run += v; }
    csum[nchunk] = run;
    rowptr[Nn] = run;
}

__global__ void rowptr_k(const int* __restrict__ deg, const int* __restrict__ csum,
                         int* __restrict__ rowptr, int Nn) {
    __shared__ int wsum[32];
    int t = threadIdx.x, lane = t & 31, wid = t >> 5;
    int i = blockIdx.x * 1024 + t;
    int v = (i < Nn) ? deg[i] : 0;
    int x = v;
    #pragma unroll
    for (int o = 1; o < 32; o <<= 1) {
        int y = __shfl_up_sync(0xffffffffu, x, o);
        if (lane >= o) x += y;
    }
    if (lane == 31) wsum[wid] = x;
    __syncthreads();
    if (wid == 0) {
        int s = wsum[lane];
        #pragma unroll
        for (int o = 1; o < 32; o <<= 1) {
            int y = __shfl_up_sync(0xffffffffu, s, o);
            if (lane >= o) s += y;
        }
        wsum[lane] = s;
    }
    __syncthreads();
    int off = csum[blockIdx.x] + (wid > 0 ? wsum[wid - 1] : 0);
    if (i < Nn) rowptr[i] = off + x - v;
}

__global__ void fill_k(const int* __restrict__ ei, int* __restrict__ cursor,
                       const int* __restrict__ rowptr, int* __restrict__ colsrc,
                       int Ein, int Etot) {
    int e = blockIdx.x * blockDim.x + threadIdx.x;
    if (e >= Etot) return;
    int s, d;
    if (e < Ein) { s = ei[e]; d = ei[Ein + e]; }
    else         { s = d = e - Ein; }
    int p = atomicAdd(&cursor[d], 1);
    colsrc[rowptr[d] + p] = s;
}

// ---------------- fused gather (unroll-4): softmax aggregate + head-mean
// + bias + LayerNorm + ReLU.  One warp per destination node. ----------------
__global__ void gather_k(const float* __restrict__ H, const int* __restrict__ rowptr,
                         const int* __restrict__ colsrc, const float* __restrict__ es,
                         const float* __restrict__ ed, const float* __restrict__ b,
                         const float* __restrict__ g, const float* __restrict__ be,
                         float* __restrict__ out, int Nn) {
    int warp = (blockIdx.x * blockDim.x + threadIdx.x) >> 5;
    int lane = threadIdx.x & 31;
    if (warp >= Nn) return;
    const int d  = warp;
    const int hA = lane >> 4;
    const int hB = hA + 2;

    float edv = (lane < 4) ? ed[d * 4 + lane] : 0.f;

    float4 a1[4], a2[4];
    float dA[4] = {0.f,0.f,0.f,0.f}, dB[4] = {0.f,0.f,0.f,0.f};
    #pragma unroll
    for (int u = 0; u < 4; u++) {
        a1[u] = make_float4(0.f,0.f,0.f,0.f);
        a2[u] = make_float4(0.f,0.f,0.f,0.f);
    }

    int beg = rowptr[d], end = rowptr[d + 1];
    const float4* __restrict__ H4 = reinterpret_cast<const float4*>(H);

    int e = beg;
    for (; e + 4 <= end; e += 4) {
        int s[4];
        #pragma unroll
        for (int u = 0; u < 4; u++) s[u] = colsrc[e + u];
        float w[4] = {0.f,0.f,0.f,0.f};
        if (lane < 4) {
            #pragma unroll
            for (int u = 0; u < 4; u++) {
                float v = es[s[u] * 4 + lane] + edv;
                v = (v > 0.f) ? v : 0.2f * v;
                w[u] = __expf(v);
            }
        }
        #pragma unroll
        for (int u = 0; u < 4; u++) {
            float wA = __shfl_sync(0xffffffffu, w[u], hA);
            float wB = __shfl_sync(0xffffffffu, w[u], hB);
            float4 h1 = H4[(long)s[u] * 64 + lane];
            float4 h2 = H4[(long)s[u] * 64 + lane + 32];
            dA[u] += wA; dB[u] += wB;
            a1[u].x += wA * h1.x; a1[u].y += wA * h1.y;
            a1[u].z += wA * h1.z; a1[u].w += wA * h1.w;
            a2[u].x += wB * h2.x; a2[u].y += wB * h2.y;
            a2[u].z += wB * h2.z; a2[u].w += wB * h2.w;
        }
    }
    for (; e < end; e++) {
        int s0 = colsrc[e];
        float w0 = 0.f;
        if (lane < 4) {
            float v = es[s0 * 4 + lane] + edv;
            v = (v > 0.f) ? v : 0.2f * v;
            w0 = __expf(v);
        }
        float wA = __shfl_sync(0xffffffffu, w0, hA);
        float wB = __shfl_sync(0xffffffffu, w0, hB);
        float4 h1 = H4[(long)s0 * 64 + lane];
        float4 h2 = H4[(long)s0 * 64 + lane + 32];
        dA[0] += wA; dB[0] += wB;
        a1[0].x += wA * h1.x; a1[0].y += wA * h1.y;
        a1[0].z += wA * h1.z; a1[0].w += wA * h1.w;
        a2[0].x += wB * h2.x; a2[0].y += wB * h2.y;
        a2[0].z += wB * h2.z; a2[0].w += wB * h2.w;
    }

    float denA = (dA[0] + dA[1]) + (dA[2] + dA[3]);
    float denB = (dB[0] + dB[1]) + (dB[2] + dB[3]);
    float4 acc1, acc2;
    acc1.x = (a1[0].x + a1[1].x) + (a1[2].x + a1[3].x);
    acc1.y = (a1[0].y + a1[1].y) + (a1[2].y + a1[3].y);
    acc1.z = (a1[0].z + a1[1].z) + (a1[2].z + a1[3].z);
    acc1.w = (a1[0].w + a1[1].w) + (a1[2].w + a1[3].w);
    acc2.x = (a2[0].x + a2[1].x) + (a2[2].x + a2[3].x);
    acc2.y = (a2[0].y + a2[1].y) + (a2[2].y + a2[3].y);
    acc2.z = (a2[0].z + a2[1].z) + (a2[2].z + a2[3].z);
    acc2.w = (a2[0].w + a2[1].w) + (a2[2].w + a2[3].w);

    float rA = 1.f / denA, rB = 1.f / denB;
    float4 s4;
    s4.x = acc1.x * rA + acc2.x * rB;
    s4.y = acc1.y * rA + acc2.y * rB;
    s4.z = acc1.z * rA + acc2.z * rB;
    s4.w = acc1.w * rA + acc2.w * rB;
    s4.x += __shfl_xor_sync(0xffffffffu, s4.x, 16);
    s4.y += __shfl_xor_sync(0xffffffffu, s4.y, 16);
    s4.z += __shfl_xor_sync(0xffffffffu, s4.z, 16);
    s4.w += __shfl_xor_sync(0xffffffffu, s4.w, 16);

    int ch = (lane & 15) * 4;
    s4.x = s4.x * 0.25f + b[ch + 0];
    s4.y = s4.y * 0.25f + b[ch + 1];
    s4.z = s4.z * 0.25f + b[ch + 2];
    s4.w = s4.w * 0.25f + b[ch + 3];

    float sum = s4.x + s4.y + s4.z + s4.w;
    float ssq = s4.x * s4.x + s4.y * s4.y + s4.z * s4.z + s4.w * s4.w;
    #pragma unroll
    for (int o = 16; o > 0; o >>= 1) {
        sum += __shfl_xor_sync(0xffffffffu, sum, o);
        ssq += __shfl_xor_sync(0xffffffffu, ssq, o);
    }
    float mean = sum * (1.f / 128.f);
    float var  = ssq * (1.f / 128.f) - mean * mean;
    float inv  = rsqrtf(var + 1e-5f);

    s4.x = fmaxf((s4.x - mean) * inv * g[ch + 0] + be[ch + 0], 0.f);
    s4.y = fmaxf((s4.y - mean) * inv * g[ch + 1] + be[ch + 1], 0.f);
    s4.z = fmaxf((s4.z - mean) * inv * g[ch + 2] + be[ch + 2], 0.f);
    s4.w = fmaxf((s4.w - mean) * inv * g[ch + 3] + be[ch + 3], 0.f);

    if (lane < 16)
        reinterpret_cast<float4*>(out + (long)d * HID)[lane] = s4;
}

// ---------------------------------------------------------------------------
extern "C" void kernel_launch(void* const* d_in, const int* in_sizes, int n_in,
                              void* d_out, int out_size) {
    const float* x     = (const float*)d_in[0];
    const int*   ei    = (const int*)  d_in[1];
    const float* W1    = (const float*)d_in[2];
    const float* asrc1 = (const float*)d_in[3];
    const float* adst1 = (const float*)d_in[4];
    const float* b1    = (const float*)d_in[5];
    const float* g1    = (const float*)d_in[6];
    const float* be1   = (const float*)d_in[7];
    const float* W2    = (const float*)d_in[8];
    const float* asrc2 = (const float*)d_in[9];
    const float* adst2 = (const float*)d_in[10];
    const float* b2    = (const float*)d_in[11];
    const float* g2    = (const float*)d_in[12];
    const float* be2   = (const float*)d_in[13];
    const float* Wo    = (const float*)d_in[14];
    const float* bo    = (const float*)d_in[15];
    float* out = (float*)d_out;

    const int Nn   = in_sizes[0] / INC;      // 50000
    const int Ein  = in_sizes[1] / 2;        // 800000
    const int Etot = Ein + Nn;               // 850000
    const int NH   = Nn * HEADS;
    const int nchunk = (Nn + 1023) / 1024;

    float *H, *ES, *ED, *F1, *F2;
    int *DEG, *CUR, *ROW, *COL, *CSUM;
    cudaGetSymbolAddress((void**)&H,    g_H);
    cudaGetSymbolAddress((void**)&ES,   g_ES);
    cudaGetSymbolAddress((void**)&ED,   g_ED);
    cudaGetSymbolAddress((void**)&F1,   g_F1);
    cudaGetSymbolAddress((void**)&F2,   g_F2);
    cudaGetSymbolAddress((void**)&DEG,  g_DEG);
    cudaGetSymbolAddress((void**)&CUR,  g_CUR);
    cudaGetSymbolAddress((void**)&ROW,  g_ROW);
    cudaGetSymbolAddress((void**)&COL,  g_COL);
    cudaGetSymbolAddress((void**)&CSUM, g_CSUM);

    dim3 gemm1_grid(HH / 128, (Nn + 127) / 128);
    dim3 gemm2_grid(HH / 128, (Nn + 127) / 128);
    dim3 gemmo_grid(OUTC / 128, (Nn + 127) / 128);

    int score_blocks = (NH * 32 + 255) / 256;
    int edge_blocks  = (Etot + 255) / 256;
    int node_warpblk = (Nn * 32 + 255) / 256;

    // ---------------- CSR build (shared by both layers) ----------------
    cudaMemsetAsync(DEG, 0, (size_t)Nn * sizeof(int), 0);
    cudaMemsetAsync(CUR, 0, (size_t)Nn * sizeof(int), 0);
    deg_k<<<edge_blocks, 256>>>(ei, DEG, Ein, Etot);
    chunksum_k<<<nchunk, 1024>>>(DEG, CSUM, Nn);
    scanchunks_k<<<1, 1>>>(CSUM, ROW, nchunk, Nn);
    rowptr_k<<<nchunk, 1024>>>(DEG, CSUM, ROW, Nn);
    fill_k<<<edge_blocks, 256>>>(ei, CUR, ROW, COL, Ein, Etot);

    // ---------------- layer 1 ----------------
    tgemm128<<<gemm1_grid, 256>>>(x, W1, H, Nn, HH, INC, nullptr);
    scores_k<<<score_blocks, 256>>>(H, asrc1, adst1, ES, ED, NH);
    gather_k<<<node_warpblk, 256>>>(H, ROW, COL, ES, ED, b1, g1, be1, F1, Nn);

    // ---------------- layer 2 ----------------
    tgemm128<<<gemm2_grid, 256>>>(F1, W2, H, Nn, HH, HID, nullptr);
    scores_k<<<score_blocks, 256>>>(H, asrc2, adst2, ES, ED, NH);
    gather_k<<<node_warpblk, 256>>>(H, ROW, COL, ES, ED, b2, g2, be2, F2, Nn);

    // ---------------- output projection ----------------
    tgemm128<<<gemmo_grid, 256>>>(F2, Wo, out, Nn, OUTC, HID, bo);
}